// round 1
// baseline (speedup 1.0000x reference)
#include <cuda_runtime.h>
#include <math.h>

#define Nn 64
#define T  512
#define Dd 512
#define Hh 512
#define G4 2048   // 4*H

// Scratch (static device allocations are the sanctioned workaround)
__device__ __align__(128) float g_xW[(size_t)Nn * T * G4];   // 256 MB: precomputed x@Wx + b
__device__ __align__(128) float g_h[2][Nn * Hh];             // ping-pong hidden state
__device__ __align__(128) float g_c[Nn * Hh];                // cell state

// ---------------------------------------------------------------------------
// GEMM 1: g_xW[M=N*T=32768][4H=2048] = x[M][512] @ Wx[512][2048] + b
// 64x64 tile, 256 threads, 4x4 per-thread microtile, BK=16.
// ---------------------------------------------------------------------------
__global__ void gemm_xw(const float* __restrict__ x,
                        const float* __restrict__ Wx,
                        const float* __restrict__ b) {
    __shared__ float As[16][68];   // [k][m], padded
    __shared__ float Bs[16][68];   // [k][n], padded

    const int tid = threadIdx.x;
    const int tx = tid & 15;       // n microtile
    const int ty = tid >> 4;       // m microtile
    const int m0 = blockIdx.y * 64;
    const int n0 = blockIdx.x * 64;

    float acc[4][4];
#pragma unroll
    for (int i = 0; i < 4; i++)
#pragma unroll
        for (int j = 0; j < 4; j++) acc[i][j] = 0.f;

    for (int k0 = 0; k0 < Dd; k0 += 16) {
        // A tile: each thread loads float4 along k for one m row
        {
            int m  = tid & 63;
            int kq = tid >> 6;   // 0..3
            float4 v = *(const float4*)&x[(size_t)(m0 + m) * Dd + k0 + kq * 4];
            As[kq * 4 + 0][m] = v.x;
            As[kq * 4 + 1][m] = v.y;
            As[kq * 4 + 2][m] = v.z;
            As[kq * 4 + 3][m] = v.w;
        }
        // B tile: coalesced float4 along n
        {
            int nq = tid & 15;
            int kk = tid >> 4;   // 0..15
            float4 v = *(const float4*)&Wx[(size_t)(k0 + kk) * G4 + n0 + nq * 4];
            *(float4*)&Bs[kk][nq * 4] = v;
        }
        __syncthreads();

#pragma unroll
        for (int kk = 0; kk < 16; kk++) {
            float4 av = *(float4*)&As[kk][ty * 4];
            float4 bv = *(float4*)&Bs[kk][tx * 4];
            float a[4] = {av.x, av.y, av.z, av.w};
            float bb[4] = {bv.x, bv.y, bv.z, bv.w};
#pragma unroll
            for (int i = 0; i < 4; i++)
#pragma unroll
                for (int j = 0; j < 4; j++) acc[i][j] += a[i] * bb[j];
        }
        __syncthreads();
    }

#pragma unroll
    for (int i = 0; i < 4; i++) {
        int m = m0 + ty * 4 + i;
#pragma unroll
        for (int j = 0; j < 4; j++) {
            int n = n0 + tx * 4 + j;
            g_xW[(size_t)m * G4 + n] = acc[i][j] + b[n];
        }
    }
}

// ---------------------------------------------------------------------------
// Init: h <- h0, c <- 0
// ---------------------------------------------------------------------------
__global__ void lstm_init(const float* __restrict__ h0) {
    int i = blockIdx.x * blockDim.x + threadIdx.x;
    if (i < Nn * Hh) {
        g_h[0][i] = h0[i];
        g_c[i]    = 0.f;
    }
}

// ---------------------------------------------------------------------------
// One recurrent step: a = xW[:,t,:] + h@Wh ; gates ; c,h update ; write out.
// Grid: 128 blocks, each owns 4 hidden columns x all 64 batch rows x 4 gates.
// Thread (n = tid/4, hc = tid%4) computes the 4 gate dot-products for (n,hc).
// ---------------------------------------------------------------------------
__global__ void lstm_step(const float* __restrict__ Wh,
                          float* __restrict__ out, int t) {
    __shared__ float hs[64][68];      // [n][k] chunk, padded
    __shared__ float ws[64][4][4];    // [k][hc][gate]

    const float* hcur = g_h[t & 1];
    float*       hnxt = g_h[(t & 1) ^ 1];

    const int tid = threadIdx.x;
    const int n   = tid >> 2;               // 0..63 batch row
    const int hc  = tid & 3;                 // 0..3 local hidden col
    const int hcg = blockIdx.x * 4 + hc;     // 0..511 global hidden col

    float acc[4] = {0.f, 0.f, 0.f, 0.f};

    for (int k0 = 0; k0 < Hh; k0 += 64) {
        // Load h chunk: 64 rows x 64 k, float4 along k
        {
            int kq = tid & 15;       // *4
            int nb = tid >> 4;       // 0..15
#pragma unroll
            for (int p = 0; p < 4; p++) {
                int nr = nb + p * 16;
                float4 v = *(const float4*)&hcur[nr * Hh + k0 + kq * 4];
                hs[nr][kq * 4 + 0] = v.x;
                hs[nr][kq * 4 + 1] = v.y;
                hs[nr][kq * 4 + 2] = v.z;
                hs[nr][kq * 4 + 3] = v.w;
            }
        }
        // Load Wh chunk: 64 k x 4 local cols x 4 gates
        {
            int k = tid >> 2;   // 0..63
            int c = tid & 3;
#pragma unroll
            for (int g = 0; g < 4; g++)
                ws[k][c][g] = Wh[(size_t)(k0 + k) * G4 + g * Hh + blockIdx.x * 4 + c];
        }
        __syncthreads();

#pragma unroll 8
        for (int k = 0; k < 64; k++) {
            float hv = hs[n][k];
            float4 w = *(float4*)&ws[k][hc][0];
            acc[0] += hv * w.x;
            acc[1] += hv * w.y;
            acc[2] += hv * w.z;
            acc[3] += hv * w.w;
        }
        __syncthreads();
    }

    // Epilogue: gates + state update
    const size_t row = (size_t)n * T + t;
    float ai = acc[0] + g_xW[row * G4 + 0 * Hh + hcg];
    float af = acc[1] + g_xW[row * G4 + 1 * Hh + hcg];
    float ao = acc[2] + g_xW[row * G4 + 2 * Hh + hcg];
    float ag = acc[3] + g_xW[row * G4 + 3 * Hh + hcg];

    float iv = 1.f / (1.f + expf(-ai));
    float fv = 1.f / (1.f + expf(-af));
    float ov = 1.f / (1.f + expf(-ao));
    float gv = tanhf(ag);

    int ci = n * Hh + hcg;
    float cn = fv * g_c[ci] + iv * gv;
    float hn = ov * tanhf(cn);

    g_c[ci]  = cn;
    hnxt[ci] = hn;
    out[row * Hh + hcg] = hn;
}

// ---------------------------------------------------------------------------
// Launch: 1 projection GEMM + init + 512 step kernels (all graph-capturable).
// ---------------------------------------------------------------------------
extern "C" void kernel_launch(void* const* d_in, const int* in_sizes, int n_in,
                              void* d_out, int out_size) {
    const float* x  = (const float*)d_in[0];
    const float* h0 = (const float*)d_in[1];
    const float* Wx = (const float*)d_in[2];
    const float* Wh = (const float*)d_in[3];
    const float* b  = (const float*)d_in[4];
    float* out = (float*)d_out;

    dim3 g1(G4 / 64, (Nn * T) / 64);   // (32, 512)
    gemm_xw<<<g1, 256>>>(x, Wx, b);
    lstm_init<<<(Nn * Hh + 255) / 256, 256>>>(h0);

    for (int t = 0; t < T; t++)
        lstm_step<<<Hh / 4, 256>>>(Wh, out, t);
}

// round 2
// speedup vs baseline: 1.0598x; 1.0598x over previous
#include <cuda_runtime.h>
#include <math.h>

#define Nn 64
#define T  512
#define Dd 512
#define Hh 512
#define G4 2048   // 4*H
#define KS 4      // k-splits in recurrent GEMM
#define CT 32     // column tiles (each owns 16 hidden units x 4 gates)

// Scratch (static device arrays are the sanctioned workaround)
__device__ __align__(128) float g_xW[(size_t)Nn * T * G4];      // 256 MB precomputed x@Wx + b
__device__ __align__(128) float g_h[2][Nn * Hh];                // ping-pong hidden state
__device__ __align__(128) float g_c[Nn * Hh];                   // cell state
__device__ __align__(128) float g_part[KS][CT][64][64];         // split-K partials [ks][ct][n][lc]
__device__ int g_cnt[CT];                                        // arrival counters (self-resetting)

// ---------------------------------------------------------------------------
// GEMM 1: g_xW[32768][2048] = x[32768][512] @ Wx[512][2048] + b
// 128x128 tile, BK=8, 256 threads, 8x8 microtile, double-buffered smem.
// ---------------------------------------------------------------------------
__global__ __launch_bounds__(256) void gemm_xw(const float* __restrict__ x,
                                               const float* __restrict__ Wx,
                                               const float* __restrict__ b) {
    __shared__ float As[2][8][128];   // [buf][k][m]
    __shared__ float Bs[2][8][128];   // [buf][k][n]

    const int tid = threadIdx.x;
    const int tx = tid & 15;          // n microtile (8 cols)
    const int ty = tid >> 4;          // m microtile (8 rows)
    const int m0 = blockIdx.y * 128;
    const int n0 = blockIdx.x * 128;

    // loader assignments
    const int a_m = tid >> 1;               // 0..127
    const int a_k = (tid & 1) * 4;          // 0 or 4
    const int b_c = (tid & 31) * 4;         // 0..124
    const int b_k = tid >> 5;               // 0..7

    float acc[8][8];
#pragma unroll
    for (int i = 0; i < 8; i++)
#pragma unroll
        for (int j = 0; j < 8; j++) acc[i][j] = 0.f;

    float4 pa = *(const float4*)&x[(size_t)(m0 + a_m) * Dd + a_k];
    float4 pb = *(const float4*)&Wx[(size_t)b_k * G4 + n0 + b_c];
    As[0][a_k + 0][a_m] = pa.x;
    As[0][a_k + 1][a_m] = pa.y;
    As[0][a_k + 2][a_m] = pa.z;
    As[0][a_k + 3][a_m] = pa.w;
    *(float4*)&Bs[0][b_k][b_c] = pb;
    __syncthreads();

    const int NSTAGE = Dd / 8;   // 64
    for (int s = 0; s < NSTAGE; s++) {
        const int cur = s & 1;
        if (s + 1 < NSTAGE) {
            const int k0 = (s + 1) * 8;
            pa = *(const float4*)&x[(size_t)(m0 + a_m) * Dd + k0 + a_k];
            pb = *(const float4*)&Wx[(size_t)(k0 + b_k) * G4 + n0 + b_c];
        }
#pragma unroll
        for (int k = 0; k < 8; k++) {
            float4 a0 = *(float4*)&As[cur][k][ty * 8];
            float4 a1 = *(float4*)&As[cur][k][ty * 8 + 4];
            float4 b0 = *(float4*)&Bs[cur][k][tx * 8];
            float4 b1 = *(float4*)&Bs[cur][k][tx * 8 + 4];
            float av[8] = {a0.x, a0.y, a0.z, a0.w, a1.x, a1.y, a1.z, a1.w};
            float bv[8] = {b0.x, b0.y, b0.z, b0.w, b1.x, b1.y, b1.z, b1.w};
#pragma unroll
            for (int i = 0; i < 8; i++)
#pragma unroll
                for (int j = 0; j < 8; j++) acc[i][j] += av[i] * bv[j];
        }
        if (s + 1 < NSTAGE) {
            const int nxt = cur ^ 1;
            As[nxt][a_k + 0][a_m] = pa.x;
            As[nxt][a_k + 1][a_m] = pa.y;
            As[nxt][a_k + 2][a_m] = pa.z;
            As[nxt][a_k + 3][a_m] = pa.w;
            *(float4*)&Bs[nxt][b_k][b_c] = pb;
            __syncthreads();
        }
    }

    // epilogue: add bias, store
    float4 bb0 = *(const float4*)&b[n0 + tx * 8];
    float4 bb1 = *(const float4*)&b[n0 + tx * 8 + 4];
#pragma unroll
    for (int i = 0; i < 8; i++) {
        size_t row = (size_t)(m0 + ty * 8 + i) * G4 + n0 + tx * 8;
        float4 o0 = make_float4(acc[i][0] + bb0.x, acc[i][1] + bb0.y,
                                acc[i][2] + bb0.z, acc[i][3] + bb0.w);
        float4 o1 = make_float4(acc[i][4] + bb1.x, acc[i][5] + bb1.y,
                                acc[i][6] + bb1.z, acc[i][7] + bb1.w);
        *(float4*)&g_xW[row] = o0;
        *(float4*)&g_xW[row + 4] = o1;
    }
}

// ---------------------------------------------------------------------------
// Init: h <- h0, c <- 0, counters <- 0
// ---------------------------------------------------------------------------
__global__ void lstm_init(const float* __restrict__ h0) {
    int i = blockIdx.x * blockDim.x + threadIdx.x;
    if (i < Nn * Hh) {
        g_h[0][i] = h0[i];
        g_c[i]    = 0.f;
    }
    if (i < CT) g_cnt[i] = 0;
}

// ---------------------------------------------------------------------------
// One recurrent step, fused split-K GEMM + last-block gate epilogue.
// grid = 128: ct = blockIdx&31 (16 hidden units x 4 gates = 64 cols),
//             ks = blockIdx>>5 (128-wide K slice).
// Block: 256 threads, 4x4 microtile over [64 batch x 64 cols].
// Dynamic smem 64KB: hs[128][64] (h slice, [k][n]) + ws[128][64] (Wh slice).
// ---------------------------------------------------------------------------
__global__ __launch_bounds__(256) void lstm_step(const float* __restrict__ Wh,
                                                 float* __restrict__ out, int t) {
    extern __shared__ float sm[];
    float* hs = sm;              // [128][64]
    float* ws = sm + 128 * 64;   // [128][64], local col lc = gate*16 + u

    const int tid = threadIdx.x;
    const int ct  = blockIdx.x & (CT - 1);
    const int ks  = blockIdx.x >> 5;
    const int k0  = ks * 128;

    const float* hcur = g_h[t & 1];
    float*       hnxt = g_h[(t & 1) ^ 1];

    // --- load h slice: hs[k][n] = hcur[n][k0+k], coalesced along k ---
    {
        const int kq = (tid & 31) * 4;
        const int nb = tid >> 5;
#pragma unroll
        for (int it = 0; it < 8; it++) {
            const int n = nb + it * 8;
            float4 v = *(const float4*)&hcur[n * Hh + k0 + kq];
            hs[(kq + 0) * 64 + n] = v.x;
            hs[(kq + 1) * 64 + n] = v.y;
            hs[(kq + 2) * 64 + n] = v.z;
            hs[(kq + 3) * 64 + n] = v.w;
        }
    }
    // --- load Wh slice: ws[k][g*16+u] = Wh[k0+k][g*512 + ct*16 + u] ---
    {
        const int u4 = (tid & 3) * 4;
        const int g  = (tid >> 2) & 3;
        const int kr = tid >> 4;        // 0..15
#pragma unroll
        for (int it = 0; it < 8; it++) {
            const int k = kr * 8 + it;
            float4 v = *(const float4*)&Wh[(size_t)(k0 + k) * G4 + g * Hh + ct * 16 + u4];
            *(float4*)&ws[k * 64 + g * 16 + u4] = v;
        }
    }
    __syncthreads();

    // --- FMA-bound main loop: 4x4 microtile ---
    const int cq = tid & 15;
    const int mq = tid >> 4;
    float acc[4][4];
#pragma unroll
    for (int i = 0; i < 4; i++)
#pragma unroll
        for (int j = 0; j < 4; j++) acc[i][j] = 0.f;

#pragma unroll 8
    for (int k = 0; k < 128; k++) {
        float4 a  = *(float4*)&hs[k * 64 + mq * 4];
        float4 bb = *(float4*)&ws[k * 64 + cq * 4];
        float av[4] = {a.x, a.y, a.z, a.w};
        float bv[4] = {bb.x, bb.y, bb.z, bb.w};
#pragma unroll
        for (int i = 0; i < 4; i++)
#pragma unroll
            for (int j = 0; j < 4; j++) acc[i][j] += av[i] * bv[j];
    }

    // --- write partial ---
#pragma unroll
    for (int i = 0; i < 4; i++)
        *(float4*)&g_part[ks][ct][mq * 4 + i][cq * 4] =
            make_float4(acc[i][0], acc[i][1], acc[i][2], acc[i][3]);

    __threadfence();   // release partials
    __shared__ int lastFlag;
    if (tid == 0) {
        int v = atomicAdd(&g_cnt[ct], 1);
        lastFlag = (v == KS - 1);
    }
    __syncthreads();
    if (!lastFlag) return;
    __threadfence();   // acquire partials
    if (tid == 0) g_cnt[ct] = 0;   // reset for next step (kernel-boundary ordered)

    // --- epilogue by last-arriving block: 16 hidden units x 64 batch ---
    const int u  = tid & 15;
    const int nb = tid >> 4;
#pragma unroll
    for (int p = 0; p < 4; p++) {
        const int n = nb + p * 16;
        float ag[4];
#pragma unroll
        for (int g = 0; g < 4; g++) {
            float s = 0.f;
#pragma unroll
            for (int q = 0; q < KS; q++) s += g_part[q][ct][n][g * 16 + u];
            ag[g] = s + g_xW[((size_t)n * T + t) * G4 + g * Hh + ct * 16 + u];
        }
        float iv = 1.f / (1.f + expf(-ag[0]));
        float fv = 1.f / (1.f + expf(-ag[1]));
        float ov = 1.f / (1.f + expf(-ag[2]));
        float gv = tanhf(ag[3]);

        const int ci = n * Hh + ct * 16 + u;
        float cn = fv * g_c[ci] + iv * gv;
        float hn = ov * tanhf(cn);
        g_c[ci]  = cn;
        hnxt[ci] = hn;
        out[((size_t)n * T + t) * Hh + ct * 16 + u] = hn;
    }
}

// ---------------------------------------------------------------------------
// Launch
// ---------------------------------------------------------------------------
extern "C" void kernel_launch(void* const* d_in, const int* in_sizes, int n_in,
                              void* d_out, int out_size) {
    const float* x  = (const float*)d_in[0];
    const float* h0 = (const float*)d_in[1];
    const float* Wx = (const float*)d_in[2];
    const float* Wh = (const float*)d_in[3];
    const float* b  = (const float*)d_in[4];
    float* out = (float*)d_out;

    cudaFuncSetAttribute(lstm_step, cudaFuncAttributeMaxDynamicSharedMemorySize, 65536);

    dim3 g1(G4 / 128, (Nn * T) / 128);   // (16, 256)
    gemm_xw<<<g1, 256>>>(x, Wx, b);
    lstm_init<<<(Nn * Hh + 255) / 256, 256>>>(h0);

    for (int t = 0; t < T; t++)
        lstm_step<<<KS * CT, 256, 65536>>>(Wh, out, t);
}

// round 3
// speedup vs baseline: 1.3800x; 1.3021x over previous
#include <cuda_runtime.h>
#include <math.h>

#define Nn 64
#define T  512
#define Dd 512
#define Hh 512
#define G4 2048   // 4*H
#define NB 128    // persistent blocks (one per SM, <=148 so co-resident)

// Scratch (static device arrays are the sanctioned workaround)
__device__ __align__(128) float g_xW[(size_t)Nn * T * G4];   // 256MB, layout [t*64+n][2048]
__device__ __align__(128) float g_h[2][Hh * Nn];             // ping-pong hidden, layout [hidx][n]
__device__ int g_cnt;
__device__ int g_epoch;

// ---------------------------------------------------------------------------
// GEMM 1: xW = x @ Wx + b, output re-laid-out as [t][n][4H] for the scan.
// 128x128 tile, BK=8, 256 threads, 8x8 microtile, double-buffered smem.
// ---------------------------------------------------------------------------
__global__ __launch_bounds__(256) void gemm_xw(const float* __restrict__ x,
                                               const float* __restrict__ Wx,
                                               const float* __restrict__ b) {
    __shared__ float As[2][8][128];
    __shared__ float Bs[2][8][128];

    const int tid = threadIdx.x;
    const int tx = tid & 15;
    const int ty = tid >> 4;
    const int m0 = blockIdx.y * 128;
    const int n0 = blockIdx.x * 128;

    const int a_m = tid >> 1;
    const int a_k = (tid & 1) * 4;
    const int b_c = (tid & 31) * 4;
    const int b_k = tid >> 5;

    float acc[8][8];
#pragma unroll
    for (int i = 0; i < 8; i++)
#pragma unroll
        for (int j = 0; j < 8; j++) acc[i][j] = 0.f;

    float4 pa = *(const float4*)&x[(size_t)(m0 + a_m) * Dd + a_k];
    float4 pb = *(const float4*)&Wx[(size_t)b_k * G4 + n0 + b_c];
    As[0][a_k + 0][a_m] = pa.x;
    As[0][a_k + 1][a_m] = pa.y;
    As[0][a_k + 2][a_m] = pa.z;
    As[0][a_k + 3][a_m] = pa.w;
    *(float4*)&Bs[0][b_k][b_c] = pb;
    __syncthreads();

    const int NSTAGE = Dd / 8;
    for (int s = 0; s < NSTAGE; s++) {
        const int cur = s & 1;
        if (s + 1 < NSTAGE) {
            const int k0 = (s + 1) * 8;
            pa = *(const float4*)&x[(size_t)(m0 + a_m) * Dd + k0 + a_k];
            pb = *(const float4*)&Wx[(size_t)(k0 + b_k) * G4 + n0 + b_c];
        }
#pragma unroll
        for (int k = 0; k < 8; k++) {
            float4 a0 = *(float4*)&As[cur][k][ty * 8];
            float4 a1 = *(float4*)&As[cur][k][ty * 8 + 4];
            float4 b0 = *(float4*)&Bs[cur][k][tx * 8];
            float4 b1 = *(float4*)&Bs[cur][k][tx * 8 + 4];
            float av[8] = {a0.x, a0.y, a0.z, a0.w, a1.x, a1.y, a1.z, a1.w};
            float bv[8] = {b0.x, b0.y, b0.z, b0.w, b1.x, b1.y, b1.z, b1.w};
#pragma unroll
            for (int i = 0; i < 8; i++)
#pragma unroll
                for (int j = 0; j < 8; j++) acc[i][j] += av[i] * bv[j];
        }
        if (s + 1 < NSTAGE) {
            const int nxt = cur ^ 1;
            As[nxt][a_k + 0][a_m] = pa.x;
            As[nxt][a_k + 1][a_m] = pa.y;
            As[nxt][a_k + 2][a_m] = pa.z;
            As[nxt][a_k + 3][a_m] = pa.w;
            *(float4*)&Bs[nxt][b_k][b_c] = pb;
            __syncthreads();
        }
    }

    float4 bb0 = *(const float4*)&b[n0 + tx * 8];
    float4 bb1 = *(const float4*)&b[n0 + tx * 8 + 4];
#pragma unroll
    for (int i = 0; i < 8; i++) {
        int m = m0 + ty * 8 + i;
        int tt = m & (T - 1);
        int nn = m >> 9;
        size_t row = ((size_t)tt * Nn + nn) * G4 + n0 + tx * 8;
        *(float4*)&g_xW[row]     = make_float4(acc[i][0] + bb0.x, acc[i][1] + bb0.y,
                                               acc[i][2] + bb0.z, acc[i][3] + bb0.w);
        *(float4*)&g_xW[row + 4] = make_float4(acc[i][4] + bb1.x, acc[i][5] + bb1.y,
                                               acc[i][6] + bb1.z, acc[i][7] + bb1.w);
    }
}

// ---------------------------------------------------------------------------
// Init: g_h[0][h][n] = h0[n][h] (transpose), reset barrier state.
// ---------------------------------------------------------------------------
__global__ void lstm_init(const float* __restrict__ h0) {
    int i = blockIdx.x * blockDim.x + threadIdx.x;
    if (i < Nn * Hh) {
        int n = i & 63;
        int h = i >> 6;
        g_h[0][h * Nn + n] = h0[n * Hh + h];
    }
    if (i == 0) { g_cnt = 0; g_epoch = 0; }
}

// ---------------------------------------------------------------------------
// Persistent scan kernel. grid=128, block=256.
// Block hb owns 16 columns: c(g,u) = g*512 + hb*4 + u  (4 hidden units x 4 gates).
// Wh slice (512k x 16c = 32KB) resident in smem for all 512 steps.
// c-state in registers. One grid barrier per step.
// smem: ws 32KB | hs double-buffer 2x(128k x 64n) 64KB | sacc 16x68 ~4.25KB
// ---------------------------------------------------------------------------
__global__ __launch_bounds__(256) void lstm_scan(const float* __restrict__ Wh,
                                                 float* __restrict__ out) {
    extern __shared__ float sm[];
    float* ws   = sm;                       // [512][16]
    float* hs   = sm + 512 * 16;            // [2][128][64]
    float* sacc = sm + 512 * 16 + 2 * 128 * 64;  // [16][68]

    const int tid = threadIdx.x;
    const int hb  = blockIdx.x;

    // main-loop thread mapping
    const int cq = tid & 15;     // local column (g*4+u)
    const int mq = tid >> 4;     // batch group of 4
    // epilogue thread mapping
    const int u_e = tid >> 6;    // 0..3 local hidden unit
    const int n_e = tid & 63;    // batch

    // --- load resident Wh slice ---
    for (int idx = tid; idx < 512 * 16; idx += 256) {
        int k = idx >> 4;
        int c = idx & 15;
        int g = c >> 2;
        int u = c & 3;
        ws[idx] = Wh[(size_t)k * G4 + g * Hh + hb * 4 + u];
    }

    float c_reg = 0.f;   // cell state for (hb*4+u_e, n_e)

    volatile int* vep = &g_epoch;

    for (int t = 0; t < T; t++) {
        const float* hcur = g_h[t & 1];
        float*       hnxt = g_h[(t & 1) ^ 1];

        // prefetch this step's xW gate slice (consumed ~8000 cycles later)
        const float* xwp = g_xW + ((size_t)t * Nn + n_e) * G4 + hb * 4 + u_e;
        float xw0 = xwp[0 * Hh];
        float xw1 = xwp[1 * Hh];
        float xw2 = xwp[2 * Hh];
        float xw3 = xwp[3 * Hh];

        // --- load h chunk 0 (32KB) ---
        {
#pragma unroll
            for (int i = 0; i < 8; i++) {
                float4 v = *(const float4*)&hcur[(i * 256 + tid) * 4];
                *(float4*)&hs[(i * 256 + tid) * 4] = v;
            }
        }
        __syncthreads();

        float acc0 = 0.f, acc1 = 0.f, acc2 = 0.f, acc3 = 0.f;

#pragma unroll
        for (int ch = 0; ch < 4; ch++) {
            const int cur = ch & 1;
            float4 pf[8];
            if (ch < 3) {
                const float* src = hcur + (ch + 1) * 128 * 64;
#pragma unroll
                for (int i = 0; i < 8; i++)
                    pf[i] = *(const float4*)&src[(i * 256 + tid) * 4];
            }
            const float* hb_cur = hs + cur * (128 * 64);
#pragma unroll 16
            for (int k = 0; k < 128; k++) {
                float4 a = *(const float4*)&hb_cur[k * 64 + mq * 4];
                float  w = ws[(ch * 128 + k) * 16 + cq];
                acc0 += a.x * w;
                acc1 += a.y * w;
                acc2 += a.z * w;
                acc3 += a.w * w;
            }
            if (ch < 3) {
                float* dst = hs + (cur ^ 1) * (128 * 64);
#pragma unroll
                for (int i = 0; i < 8; i++)
                    *(float4*)&dst[(i * 256 + tid) * 4] = pf[i];
                __syncthreads();
            }
        }

        // --- gather partials across columns in smem ---
        *(float4*)&sacc[cq * 68 + mq * 4] = make_float4(acc0, acc1, acc2, acc3);
        __syncthreads();

        // --- epilogue: thread handles (u_e, n_e) ---
        {
            float ai = sacc[(0 * 4 + u_e) * 68 + n_e] + xw0;
            float af = sacc[(1 * 4 + u_e) * 68 + n_e] + xw1;
            float ao = sacc[(2 * 4 + u_e) * 68 + n_e] + xw2;
            float ag = sacc[(3 * 4 + u_e) * 68 + n_e] + xw3;

            float iv = 1.f / (1.f + expf(-ai));
            float fv = 1.f / (1.f + expf(-af));
            float ov = 1.f / (1.f + expf(-ao));
            float gv = tanhf(ag);

            c_reg = fv * c_reg + iv * gv;
            float hn = ov * tanhf(c_reg);

            hnxt[(hb * 4 + u_e) * Nn + n_e] = hn;
            out[((size_t)n_e * T + t) * Hh + hb * 4 + u_e] = hn;
        }
        __syncthreads();   // protect sacc + ensure all h-reads of this step done

        // --- grid barrier (epoch t+1) ---
        if (tid == 0) {
            __threadfence();
            int v = atomicAdd(&g_cnt, 1);
            if (v == NB - 1) {
                g_cnt = 0;
                __threadfence();
                *vep = t + 1;
            } else {
                while (*vep < t + 1) { }
            }
            __threadfence();
        }
        __syncthreads();
    }
}

// ---------------------------------------------------------------------------
// Launch: gemm + init + ONE persistent scan kernel.
// ---------------------------------------------------------------------------
extern "C" void kernel_launch(void* const* d_in, const int* in_sizes, int n_in,
                              void* d_out, int out_size) {
    const float* x  = (const float*)d_in[0];
    const float* h0 = (const float*)d_in[1];
    const float* Wx = (const float*)d_in[2];
    const float* Wh = (const float*)d_in[3];
    const float* b  = (const float*)d_in[4];
    float* out = (float*)d_out;

    const int smem = (512 * 16 + 2 * 128 * 64 + 16 * 68) * sizeof(float);
    static int configured = 0;
    cudaFuncSetAttribute(lstm_scan, cudaFuncAttributeMaxDynamicSharedMemorySize, smem);
    (void)configured;

    dim3 g1(G4 / 128, (Nn * T) / 128);
    gemm_xw<<<g1, 256>>>(x, Wx, b);
    lstm_init<<<(Nn * Hh + 255) / 256, 256>>>(h0);
    lstm_scan<<<NB, 256, smem>>>(Wh, out);
}

// round 4
// speedup vs baseline: 1.6805x; 1.2177x over previous
#include <cuda_runtime.h>
#include <math.h>

#define Nn 64
#define T  512
#define Dd 512
#define Hh 512
#define G4 2048   // 4*H
#define NB 128    // persistent blocks (<=148 SMs, co-resident)

// Scratch (static device arrays are the sanctioned workaround)
__device__ __align__(128) float g_xW[(size_t)Nn * T * G4];   // [t][n][4H]
__device__ __align__(128) float g_h[2][Hh * Nn];             // ping-pong hidden, [hidx][n]
__device__ int g_cnt;
__device__ int g_epoch;

// Packed dual-lane fp32 FMA (Blackwell FFMA2; only reachable via PTX f32x2)
__device__ __forceinline__ void fma2(unsigned long long& d,
                                     unsigned long long a,
                                     unsigned long long b) {
    asm("fma.rn.f32x2 %0, %1, %2, %0;" : "+l"(d) : "l"(a), "l"(b));
}
__device__ __forceinline__ float2 u2f2(unsigned long long v) {
    float2 r;
    asm("mov.b64 {%0,%1}, %2;" : "=f"(r.x), "=f"(r.y) : "l"(v));
    return r;
}

// ---------------------------------------------------------------------------
// GEMM 1: xW = x @ Wx + b, relaid as [t][n][4H].
// 128x128 tile, BK=8, 256 threads, 8x8 microtile via f32x2, double-buffered.
// ---------------------------------------------------------------------------
__global__ __launch_bounds__(256) void gemm_xw(const float* __restrict__ x,
                                               const float* __restrict__ Wx,
                                               const float* __restrict__ b) {
    __shared__ float Ad[2][8][256];   // duplicated pairs: [buf][k][m*2+{0,1}]
    __shared__ float Bs[2][8][128];

    const int tid = threadIdx.x;
    const int tx = tid & 15;
    const int ty = tid >> 4;
    const int m0 = blockIdx.y * 128;
    const int n0 = blockIdx.x * 128;

    const int a_m = tid >> 1;
    const int a_k = (tid & 1) * 4;
    const int b_c = (tid & 31) * 4;
    const int b_k = tid >> 5;

    unsigned long long acc[8][4];
#pragma unroll
    for (int i = 0; i < 8; i++)
#pragma unroll
        for (int j = 0; j < 4; j++) acc[i][j] = 0ULL;

    float4 pa = *(const float4*)&x[(size_t)(m0 + a_m) * Dd + a_k];
    float4 pb = *(const float4*)&Wx[(size_t)b_k * G4 + n0 + b_c];
    *(float2*)&Ad[0][a_k + 0][a_m * 2] = make_float2(pa.x, pa.x);
    *(float2*)&Ad[0][a_k + 1][a_m * 2] = make_float2(pa.y, pa.y);
    *(float2*)&Ad[0][a_k + 2][a_m * 2] = make_float2(pa.z, pa.z);
    *(float2*)&Ad[0][a_k + 3][a_m * 2] = make_float2(pa.w, pa.w);
    *(float4*)&Bs[0][b_k][b_c] = pb;
    __syncthreads();

    const int NSTAGE = Dd / 8;
    for (int s = 0; s < NSTAGE; s++) {
        const int cur = s & 1;
        if (s + 1 < NSTAGE) {
            const int k0 = (s + 1) * 8;
            pa = *(const float4*)&x[(size_t)(m0 + a_m) * Dd + k0 + a_k];
            pb = *(const float4*)&Wx[(size_t)(k0 + b_k) * G4 + n0 + b_c];
        }
#pragma unroll
        for (int k = 0; k < 8; k++) {
            const unsigned long long* ap =
                (const unsigned long long*)&Ad[cur][k][0];
            ulonglong2 a01 = *(const ulonglong2*)&ap[ty * 8 + 0];
            ulonglong2 a23 = *(const ulonglong2*)&ap[ty * 8 + 2];
            ulonglong2 a45 = *(const ulonglong2*)&ap[ty * 8 + 4];
            ulonglong2 a67 = *(const ulonglong2*)&ap[ty * 8 + 6];
            ulonglong2 w01 = *(const ulonglong2*)&Bs[cur][k][tx * 8];
            ulonglong2 w23 = *(const ulonglong2*)&Bs[cur][k][tx * 8 + 4];
            unsigned long long av[8] = {a01.x, a01.y, a23.x, a23.y,
                                        a45.x, a45.y, a67.x, a67.y};
            unsigned long long wv[4] = {w01.x, w01.y, w23.x, w23.y};
#pragma unroll
            for (int i = 0; i < 8; i++)
#pragma unroll
                for (int j = 0; j < 4; j++) fma2(acc[i][j], av[i], wv[j]);
        }
        if (s + 1 < NSTAGE) {
            const int nxt = cur ^ 1;
            *(float2*)&Ad[nxt][a_k + 0][a_m * 2] = make_float2(pa.x, pa.x);
            *(float2*)&Ad[nxt][a_k + 1][a_m * 2] = make_float2(pa.y, pa.y);
            *(float2*)&Ad[nxt][a_k + 2][a_m * 2] = make_float2(pa.z, pa.z);
            *(float2*)&Ad[nxt][a_k + 3][a_m * 2] = make_float2(pa.w, pa.w);
            *(float4*)&Bs[nxt][b_k][b_c] = pb;
            __syncthreads();
        }
    }

    float4 bb0 = *(const float4*)&b[n0 + tx * 8];
    float4 bb1 = *(const float4*)&b[n0 + tx * 8 + 4];
#pragma unroll
    for (int i = 0; i < 8; i++) {
        int m = m0 + ty * 8 + i;
        int tt = m & (T - 1);
        int nn = m >> 9;
        size_t row = ((size_t)tt * Nn + nn) * G4 + n0 + tx * 8;
        float2 p0 = u2f2(acc[i][0]);
        float2 p1 = u2f2(acc[i][1]);
        float2 p2 = u2f2(acc[i][2]);
        float2 p3 = u2f2(acc[i][3]);
        *(float4*)&g_xW[row]     = make_float4(p0.x + bb0.x, p0.y + bb0.y,
                                               p1.x + bb0.z, p1.y + bb0.w);
        *(float4*)&g_xW[row + 4] = make_float4(p2.x + bb1.x, p2.y + bb1.y,
                                               p3.x + bb1.z, p3.y + bb1.w);
    }
}

// ---------------------------------------------------------------------------
// Init: g_h[0][h][n] = h0[n][h]; reset barrier state.
// ---------------------------------------------------------------------------
__global__ void lstm_init(const float* __restrict__ h0) {
    int i = blockIdx.x * blockDim.x + threadIdx.x;
    if (i < Nn * Hh) {
        int n = i & 63;
        int h = i >> 6;
        g_h[0][h * Nn + n] = h0[n * Hh + h];
    }
    if (i == 0) { g_cnt = 0; g_epoch = 0; }
}

// ---------------------------------------------------------------------------
// Persistent scan. grid=128, block=256. Block hb owns 16 columns
// (4 hidden units x 4 gates). smem: Wh pairs 64KB | full h 128KB | sacc | hstage.
// Intra-block K-split(4), 4col x 4batch microtile via f32x2.
// ---------------------------------------------------------------------------
__global__ __launch_bounds__(256) void lstm_scan(const float* __restrict__ Wh,
                                                 float* __restrict__ out) {
    extern __shared__ float sm[];
    unsigned long long* wsd = (unsigned long long*)sm;        // [512][16] dup pairs
    float* hfull  = sm + 512 * 16 * 2;                        // [512][64]
    float* sacc   = hfull + 512 * 64;                         // [4][16][66]
    float* hstage = sacc + 4 * 16 * 66;                       // [64][4]

    const int tid = threadIdx.x;
    const int hb  = blockIdx.x;
    const int ks  = tid >> 6;          // K slice 0..3
    const int r   = tid & 63;
    const int mq  = r & 15;            // batch group of 4
    const int cq  = r >> 4;            // col group of 4
    const int u_e = tid >> 6;          // epilogue: local hidden unit
    const int n_e = tid & 63;          // epilogue: batch

    // resident Wh slice, duplicated pairs {w,w}
    for (int idx = tid; idx < 512 * 16; idx += 256) {
        int k = idx >> 4;
        int c = idx & 15;
        int g = c >> 2;
        int u = c & 3;
        float w = Wh[(size_t)k * G4 + g * Hh + hb * 4 + u];
        ((float2*)wsd)[idx] = make_float2(w, w);
    }

    float c_reg = 0.f;
    volatile int* vep = &g_epoch;

    for (int t = 0; t < T; t++) {
        const float* hcur = g_h[t & 1];
        float*       hnxt = g_h[(t & 1) ^ 1];

        // prefetch this step's xW gate slice
        const float* xwp = g_xW + ((size_t)t * Nn + n_e) * G4 + hb * 4 + u_e;
        float xw0 = xwp[0 * Hh];
        float xw1 = xwp[1 * Hh];
        float xw2 = xwp[2 * Hh];
        float xw3 = xwp[3 * Hh];

        // load full h (128KB), coalesced
#pragma unroll
        for (int i = 0; i < 32; i++) {
            int idx = (i * 256 + tid) * 4;
            *(float4*)&hfull[idx] = *(const float4*)&hcur[idx];
        }
        __syncthreads();

        // GEMM slice: cols [cq*4..cq*4+3], batches [mq*4..mq*4+3], k slice ks
        unsigned long long acc00 = 0, acc01 = 0, acc10 = 0, acc11 = 0;
        unsigned long long acc20 = 0, acc21 = 0, acc30 = 0, acc31 = 0;
        const float* hbase = hfull + ks * 128 * 64 + mq * 4;
        const unsigned long long* wbase = wsd + ks * 128 * 16 + cq * 4;
#pragma unroll 8
        for (int k = 0; k < 128; k++) {
            ulonglong2 a  = *(const ulonglong2*)(hbase + (size_t)k * 64);
            ulonglong2 w0 = *(const ulonglong2*)(wbase + k * 16);
            ulonglong2 w1 = *(const ulonglong2*)(wbase + k * 16 + 2);
            fma2(acc00, w0.x, a.x); fma2(acc01, w0.x, a.y);
            fma2(acc10, w0.y, a.x); fma2(acc11, w0.y, a.y);
            fma2(acc20, w1.x, a.x); fma2(acc21, w1.x, a.y);
            fma2(acc30, w1.y, a.x); fma2(acc31, w1.y, a.y);
        }

        // partials -> smem
        {
            float* p0 = &sacc[(ks * 16 + cq * 4 + 0) * 66 + mq * 4];
            float* p1 = &sacc[(ks * 16 + cq * 4 + 1) * 66 + mq * 4];
            float* p2 = &sacc[(ks * 16 + cq * 4 + 2) * 66 + mq * 4];
            float* p3 = &sacc[(ks * 16 + cq * 4 + 3) * 66 + mq * 4];
            *(unsigned long long*)(p0)     = acc00;
            *(unsigned long long*)(p0 + 2) = acc01;
            *(unsigned long long*)(p1)     = acc10;
            *(unsigned long long*)(p1 + 2) = acc11;
            *(unsigned long long*)(p2)     = acc20;
            *(unsigned long long*)(p2 + 2) = acc21;
            *(unsigned long long*)(p3)     = acc30;
            *(unsigned long long*)(p3 + 2) = acc31;
        }
        __syncthreads();

        // epilogue: thread handles (u_e, n_e)
        {
            float ag[4];
#pragma unroll
            for (int g = 0; g < 4; g++) {
                int c = g * 4 + u_e;
                float s = sacc[(0 * 16 + c) * 66 + n_e]
                        + sacc[(1 * 16 + c) * 66 + n_e]
                        + sacc[(2 * 16 + c) * 66 + n_e]
                        + sacc[(3 * 16 + c) * 66 + n_e];
                ag[g] = s;
            }
            ag[0] += xw0; ag[1] += xw1; ag[2] += xw2; ag[3] += xw3;

            float iv = 1.f / (1.f + expf(-ag[0]));
            float fv = 1.f / (1.f + expf(-ag[1]));
            float ov = 1.f / (1.f + expf(-ag[2]));
            float gv = tanhf(ag[3]);

            c_reg = fv * c_reg + iv * gv;
            float hn = ov * tanhf(c_reg);

            hnxt[(hb * 4 + u_e) * Nn + n_e] = hn;
            hstage[n_e * 4 + u_e] = hn;
        }
        __syncthreads();

        // coalesced out write: out[n][t][hb*4..hb*4+3]
        if (tid < 64)
            *(float4*)&out[((size_t)tid * T + t) * Hh + hb * 4] =
                *(float4*)&hstage[tid * 4];

        // grid barrier (epoch t+1); thread0 fence also flushes L1D (CCTL.IVALL)
        if (tid == 0) {
            __threadfence();
            int v = atomicAdd(&g_cnt, 1);
            if (v == NB - 1) {
                g_cnt = 0;
                __threadfence();
                *vep = t + 1;
            } else {
                while (*vep < t + 1) { }
            }
            __threadfence();
        }
        __syncthreads();
    }
}

// ---------------------------------------------------------------------------
// Launch
// ---------------------------------------------------------------------------
extern "C" void kernel_launch(void* const* d_in, const int* in_sizes, int n_in,
                              void* d_out, int out_size) {
    const float* x  = (const float*)d_in[0];
    const float* h0 = (const float*)d_in[1];
    const float* Wx = (const float*)d_in[2];
    const float* Wh = (const float*)d_in[3];
    const float* b  = (const float*)d_in[4];
    float* out = (float*)d_out;

    const int smem = (512 * 16 * 2 + 512 * 64 + 4 * 16 * 66 + 64 * 4) * sizeof(float);
    cudaFuncSetAttribute(lstm_scan, cudaFuncAttributeMaxDynamicSharedMemorySize, smem);

    dim3 g1(G4 / 128, (Nn * T) / 128);
    gemm_xw<<<g1, 256>>>(x, Wx, b);
    lstm_init<<<(Nn * Hh + 255) / 256, 256>>>(h0);
    lstm_scan<<<NB, 256, smem>>>(Wh, out);
}